// round 4
// baseline (speedup 1.0000x reference)
#include <cuda_runtime.h>
#include <cstdint>

#define BB 4
#define TT 1024
#define DD 768
#define LL 4
#define DFF 3072
#define VV 50257
#define NB 148
#define NT 512
#define NWARP (NB * (NT / 32))   // 2368 warps (k_main)
#define LSTRIDE 50260            // VV padded to multiple of 4

// ---------------- scratch (static __device__, no allocations) ----------------
__device__ float g_kwm[DD];
__device__ float g_kbm;
__device__ float g_kmean[BB * TT];
__device__ float g_w[BB * TT];
__device__ float g_xpart[BB * 32 * DD];
__device__ float g_pA[96 * BB * DD];
__device__ float g_pB[96 * BB * DD];
__device__ __align__(16) float g_xn[BB * DD];
__device__ __align__(16) float g_logits[BB * LSTRIDE];

__device__ unsigned g_arrive;
__device__ unsigned g_phase;

__device__ __forceinline__ float warp_sum(float v) {
    #pragma unroll
    for (int o = 16; o; o >>= 1) v += __shfl_xor_sync(0xffffffffu, v, o);
    return v;
}

// grid-wide barrier: all NB blocks co-resident (1 block/SM).
__device__ __forceinline__ void gsync() {
    __syncthreads();
    if (threadIdx.x == 0) {
        volatile unsigned* ph = &g_phase;
        unsigned gen = *ph;
        __threadfence();
        if (atomicAdd(&g_arrive, 1u) == NB - 1) {
            g_arrive = 0;
            __threadfence();
            *ph = gen + 1;
        } else {
            while (*ph == gen) { }
        }
        __threadfence();
    }
    __syncthreads();
}

// ---- skinny GEMM stage; W prefetched to registers BEFORE input reduction ----
// dst[(kch*4+b)*N + n] = sum over this k-chunk of x[b,k]*W[k,n], where x is
// reduced on the fly from xpart (32 chunks) or previous split-K partials.
template<int KC>
__device__ __forceinline__ void gemm_stage(int srcXpart, const float* __restrict__ src,
                                           int srcKCH, const float* __restrict__ bias,
                                           int act, const float* __restrict__ W,
                                           int K, int N, int NC,
                                           float* __restrict__ dst, float* sA) {
    int blk = blockIdx.x, tid = threadIdx.x;
    int nblocks = NC * ((K / KC) / 2);
    if (blk < nblocks) {
        int nc = blk % NC;
        int kpair = blk / NC;
        int sub = tid >> 8;
        int n = nc * 256 + (tid & 255);
        int kch = kpair * 2 + sub;

        // prefetch W column slice (independent LDGs, deep MLP) — overlaps with
        // the partials reduction below.
        const float* Wp = W + (size_t)(kch * KC) * N + n;
        float wreg[KC];
        #pragma unroll
        for (int kk = 0; kk < KC; kk++) wreg[kk] = Wp[(size_t)kk * N];

        // fused input reduction into smem
        for (int i = tid; i < 8 * KC; i += NT) {
            int s2 = i / (4 * KC);
            int rem = i - s2 * 4 * KC;
            int b = rem / KC, kk = rem - b * KC;
            int kg = (kpair * 2 + s2) * KC + kk;
            float v = 0.f;
            if (srcXpart) {
                #pragma unroll 8
                for (int c = 0; c < 32; c++)
                    v += g_xpart[(size_t)(b * 32 + c) * DD + kg];
            } else {
                #pragma unroll 8
                for (int kc = 0; kc < srcKCH; kc++)
                    v += src[((size_t)kc * BB + b) * K + kg];
            }
            if (bias) v += bias[kg];
            if (act) v = 0.5f * v * (1.0f + erff(v * 0.70710678118654752f));
            sA[(s2 * 4 + b) * KC + kk] = v;
        }
        __syncthreads();

        const float* a = sA + sub * 4 * KC;
        float a0 = 0.f, a1 = 0.f, a2 = 0.f, a3 = 0.f;
        #pragma unroll
        for (int kk = 0; kk < KC; kk++) {
            float w = wreg[kk];
            a0 += a[kk] * w;
            a1 += a[KC + kk] * w;
            a2 += a[2 * KC + kk] * w;
            a3 += a[3 * KC + kk] * w;
        }
        size_t base = (size_t)kch * BB * N + n;
        dst[base]         = a0;
        dst[base + N]     = a1;
        dst[base + 2 * N] = a2;
        dst[base + 3 * N] = a3;
        __syncthreads();
    }
}

// =================== persistent kernel: embeddings ... ln_f ==================
__global__ __launch_bounds__(NT, 1)
void k_main(const int* __restrict__ idx, const float* __restrict__ wte,
            const float* __restrict__ wpe, const float* __restrict__ lnw,
            const float* __restrict__ kw,  const float* __restrict__ kb,
            const float* __restrict__ vw,  const float* __restrict__ vb,
            const float* __restrict__ fcw, const float* __restrict__ pw) {
    __shared__ float sm[BB * DD];
    __shared__ int   smi[32];
    int blk = blockIdx.x, tid = threadIdx.x;
    int lane = tid & 31, wid = tid >> 5;
    int gw = blk * (NT / 32) + wid;

    // S0: kwm[i] = mean_d kw0[i,d]; kbm = mean(kb0)
    for (int i = gw; i < DD; i += NWARP) {
        const float* row = kw + (size_t)i * DD;
        float s = 0.f;
        #pragma unroll
        for (int jj = 0; jj < DD / 32; jj++) s += row[lane + jj * 32];
        s = warp_sum(s);
        if (lane == 0) g_kwm[i] = s * (1.0f / DD);
    }
    if (gw == NWARP - 1) {
        float s = 0.f;
        #pragma unroll
        for (int jj = 0; jj < DD / 32; jj++) s += kb[lane + jj * 32];
        s = warp_sum(s);
        if (lane == 0) g_kbm = s * (1.0f / DD);
    }
    gsync();

    // S1: k_mean[b,t] = (wte[idx]+wpe[t]) . kwm + kbm
    for (int i = tid; i < DD; i += NT) sm[i] = g_kwm[i];
    __syncthreads();
    for (int tok = gw; tok < BB * TT; tok += NWARP) {
        int t = tok & (TT - 1);
        const float* e = wte + (size_t)idx[tok] * DD;
        const float* p = wpe + (size_t)t * DD;
        float s = 0.f;
        #pragma unroll
        for (int jj = 0; jj < DD / 32; jj++) {
            int j = lane + jj * 32;
            s += (e[j] + p[j]) * sm[j];
        }
        s = warp_sum(s);
        if (lane == 0) g_kmean[tok] = s + g_kbm;
    }
    gsync();

    // S2: softmax over T of cos(k_mean), per batch
    if (blk < BB) {
        float v0 = cosf(g_kmean[blk * TT + tid]);
        float v1 = cosf(g_kmean[blk * TT + tid + 512]);
        sm[tid] = fmaxf(v0, v1); __syncthreads();
        for (int o = 256; o; o >>= 1) { if (tid < o) sm[tid] = fmaxf(sm[tid], sm[tid + o]); __syncthreads(); }
        float mx = sm[0]; __syncthreads();
        float e0 = expf(v0 - mx), e1 = expf(v1 - mx);
        sm[tid] = e0 + e1; __syncthreads();
        for (int o = 256; o; o >>= 1) { if (tid < o) sm[tid] += sm[tid + o]; __syncthreads(); }
        float inv = 1.0f / sm[0];
        g_w[blk * TT + tid]       = e0 * inv;
        g_w[blk * TT + tid + 512] = e1 * inv;
    }
    gsync();

    // S3: xbar partials
    if (blk < 128) {
        int b = blk >> 5, c = blk & 31;
        if (tid < 32) {
            int t = c * 32 + tid;
            sm[tid]  = g_w[b * TT + t];
            smi[tid] = idx[b * TT + t];
        }
        __syncthreads();
        for (int d = tid; d < DD; d += NT) {
            float acc = 0.f;
            #pragma unroll 8
            for (int j = 0; j < 32; j++) {
                int t = c * 32 + j;
                acc += sm[j] * (wte[(size_t)smi[j] * DD + d] + wpe[(size_t)t * DD + d]);
            }
            g_xpart[(size_t)blk * DD + d] = acc;
        }
    }
    gsync();

    // 4 layers, split-K partials ping-pong; reductions fused into consumers.
    float* P[2] = {g_pA, g_pB};
    int xb = -1;
    for (int l = 0; l < LL; l++) {
        const float* vwl  = vw  + (size_t)l * DD * DD;
        const float* vbl  = vb  + (size_t)l * DD;
        const float* fcwl = fcw + (size_t)l * DD * DFF;
        const float* pwl  = pw  + (size_t)l * DFF * DD;

        float* d0 = (xb == 1) ? P[0] : ((xb == 0) ? P[1] : P[0]);
        float* d1 = (d0 == P[0]) ? P[1] : P[0];
        const float* xsrc = (xb < 0) ? nullptr : P[xb];

        gemm_stage<8>(xb < 0, xsrc, 96, nullptr, 0, vwl, DD, DD, 3, d0, sm);
        gsync();
        gemm_stage<32>(0, d0, 96, vbl, 0, fcwl, DD, DFF, 12, d1, sm);
        gsync();
        gemm_stage<32>(0, d1, 24, nullptr, 1, pwl, DFF, DD, 3, d0, sm);
        gsync();
        xb = (d0 == P[0]) ? 0 : 1;
    }

    // ln_f (blocks 0..3), reducing final partials
    if (blk < BB) {
        const float* Px = P[xb];
        float v0 = 0.f, v1 = 0.f;
        #pragma unroll 8
        for (int kc = 0; kc < 96; kc++)
            v0 += Px[((size_t)kc * BB + blk) * DD + tid];
        if (tid < 256) {
            #pragma unroll 8
            for (int kc = 0; kc < 96; kc++)
                v1 += Px[((size_t)kc * BB + blk) * DD + tid + 512];
        }
        sm[tid] = v0 + v1; __syncthreads();
        for (int o = 256; o; o >>= 1) { if (tid < o) sm[tid] += sm[tid + o]; __syncthreads(); }
        float mu = sm[0] * (1.0f / DD); __syncthreads();
        float d0 = v0 - mu, d1 = (tid < 256) ? (v1 - mu) : 0.f;
        sm[tid] = d0 * d0 + ((tid < 256) ? d1 * d1 : 0.f); __syncthreads();
        for (int o = 256; o; o >>= 1) { if (tid < o) sm[tid] += sm[tid + o]; __syncthreads(); }
        float rstd = rsqrtf(sm[0] * (1.0f / DD) + 1e-5f);
        g_xn[blk * DD + tid] = d0 * rstd * lnw[tid];
        if (tid < 256) g_xn[blk * DD + tid + 512] = d1 * rstd * lnw[tid + 512];
    }
}

// ========== cooperative lm_head + broadcast (148 blocks, 1/SM) ===============
// Phase A: logits[b,v] = xn[b,:].wte[v,:]  (all blocks, warp per vocab row)
// gsync
// Phase B: block = (batch, row-group); batch logits in 201KB dynamic smem;
//          rows streamed with aligned STG.128 built from two aligned LDS.128.
__global__ __launch_bounds__(1024, 1)
void k_bcast(const float* __restrict__ wte, float* __restrict__ out) {
    extern __shared__ __align__(16) float smf[];   // LSTRIDE floats
    __shared__ float4 sxn4[BB * DD / 4];           // 12 KB
    float4* sm4 = (float4*)smf;
    int tid = threadIdx.x, wid = tid >> 5, lane = tid & 31;
    int blk = blockIdx.x;

    // ---- Phase A ----
    for (int i = tid; i < BB * DD / 4; i += 1024)
        sxn4[i] = ((const float4*)g_xn)[i];
    __syncthreads();
    int gw = blk * 32 + wid;                       // 0..4735
    for (int v = gw; v < VV; v += NB * 32) {
        const float4* wr = (const float4*)(wte + (size_t)v * DD);
        float a0 = 0.f, a1 = 0.f, a2 = 0.f, a3 = 0.f;
        #pragma unroll
        for (int jj = 0; jj < DD / 128; jj++) {
            int j = lane + jj * 32;
            float4 w = wr[j];
            float4 x0 = sxn4[j];
            float4 x1 = sxn4[192 + j];
            float4 x2 = sxn4[384 + j];
            float4 x3 = sxn4[576 + j];
            a0 += w.x * x0.x + w.y * x0.y + w.z * x0.z + w.w * x0.w;
            a1 += w.x * x1.x + w.y * x1.y + w.z * x1.z + w.w * x1.w;
            a2 += w.x * x2.x + w.y * x2.y + w.z * x2.z + w.w * x2.w;
            a3 += w.x * x3.x + w.y * x3.y + w.z * x3.z + w.w * x3.w;
        }
        a0 = warp_sum(a0); a1 = warp_sum(a1); a2 = warp_sum(a2); a3 = warp_sum(a3);
        if (lane == 0) {
            g_logits[v]               = a0;
            g_logits[LSTRIDE + v]     = a1;
            g_logits[2 * LSTRIDE + v] = a2;
            g_logits[3 * LSTRIDE + v] = a3;
        }
    }
    gsync();

    // ---- Phase B ----
    int batch = blk & 3, grp = blk >> 2;           // 37 groups per batch
    const float4* src4 = (const float4*)(g_logits + (size_t)batch * LSTRIDE);
    for (int i = tid; i < LSTRIDE / 4; i += 1024) sm4[i] = src4[i];
    __syncthreads();

    for (int r = grp; r < TT; r += 37) {
        float* dst = out + (size_t)(batch * TT + r) * VV;
        int p = (4 - (r & 3)) & 3;                 // constant per row
        if (tid < p) dst[tid] = smf[tid];
        int nvec = (VV - p) >> 2;
        float4* d4 = (float4*)(dst + p);
        if (p == 0) {
            for (int i = tid; i < nvec; i += 1024) __stcs(d4 + i, sm4[i]);
        } else if (p == 1) {
            for (int i = tid; i < nvec; i += 1024) {
                float4 a = sm4[i], b = sm4[i + 1];
                __stcs(d4 + i, make_float4(a.y, a.z, a.w, b.x));
            }
        } else if (p == 2) {
            for (int i = tid; i < nvec; i += 1024) {
                float4 a = sm4[i], b = sm4[i + 1];
                __stcs(d4 + i, make_float4(a.z, a.w, b.x, b.y));
            }
        } else {
            for (int i = tid; i < nvec; i += 1024) {
                float4 a = sm4[i], b = sm4[i + 1];
                __stcs(d4 + i, make_float4(a.w, b.x, b.y, b.z));
            }
        }
        int done = p + 4 * nvec;
        int rem = VV - done;
        if (tid < rem) dst[done + tid] = smf[done + tid];
    }
}

// ---------------- launch ------------------------------------------------------
extern "C" void kernel_launch(void* const* d_in, const int* in_sizes, int n_in,
                              void* d_out, int out_size) {
    const int*   idx = (const int*)  d_in[0];
    const float* wte = (const float*)d_in[1];
    const float* wpe = (const float*)d_in[2];
    const float* lnw = (const float*)d_in[3];
    // d_in[4]=qw, d_in[5]=qb : dead (scores independent of Q)
    const float* kw  = (const float*)d_in[6];
    const float* kb  = (const float*)d_in[7];
    const float* vw  = (const float*)d_in[8];
    const float* vb  = (const float*)d_in[9];
    const float* fcw = (const float*)d_in[10];
    const float* pw  = (const float*)d_in[11];
    float* out = (float*)d_out;

    const int smbytes = LSTRIDE * 4;   // 201040 B dynamic smem
    cudaFuncSetAttribute(k_bcast, cudaFuncAttributeMaxDynamicSharedMemorySize, smbytes);

    k_main<<<NB, NT>>>(idx, wte, wpe, lnw, kw, kb, vw, vb, fcw, pw);
    k_bcast<<<NB, 1024, smbytes>>>(wte, out);
}

// round 5
// speedup vs baseline: 1.2028x; 1.2028x over previous
#include <cuda_runtime.h>
#include <cstdint>

#define BB 4
#define TT 1024
#define DD 768
#define LL 4
#define DFF 3072
#define VV 50257
#define NB 148
#define NT 512
#define NWARP (NB * (NT / 32))   // 2368 warps (k_main)
#define LSTRIDE 50260            // VV padded to multiple of 4
#define WIN 4096                 // broadcast column window (floats)
#define NWIN 13                  // ceil(VV / WIN)
#define RG 16                    // row groups (64 rows each)

// ---------------- scratch (static __device__, no allocations) ----------------
__device__ float g_kwm[DD];
__device__ float g_kbm;
__device__ float g_kmean[BB * TT];
__device__ float g_w[BB * TT];
__device__ float g_xpart[BB * 32 * DD];
__device__ float g_pA[96 * BB * DD];
__device__ float g_pB[96 * BB * DD];
__device__ __align__(16) float g_xn[BB * DD];
__device__ __align__(16) float g_logits[BB * LSTRIDE];

__device__ unsigned g_arrive;
__device__ unsigned g_phase;

__device__ __forceinline__ float warp_sum(float v) {
    #pragma unroll
    for (int o = 16; o; o >>= 1) v += __shfl_xor_sync(0xffffffffu, v, o);
    return v;
}

// grid-wide barrier: all NB blocks co-resident (1 block/SM).
__device__ __forceinline__ void gsync() {
    __syncthreads();
    if (threadIdx.x == 0) {
        volatile unsigned* ph = &g_phase;
        unsigned gen = *ph;
        __threadfence();
        if (atomicAdd(&g_arrive, 1u) == NB - 1) {
            g_arrive = 0;
            __threadfence();
            *ph = gen + 1;
        } else {
            while (*ph == gen) { }
        }
        __threadfence();
    }
    __syncthreads();
}

// ---- skinny GEMM stage; W prefetched to registers BEFORE input reduction ----
template<int KC>
__device__ __forceinline__ void gemm_stage(int srcXpart, const float* __restrict__ src,
                                           int srcKCH, const float* __restrict__ bias,
                                           int act, const float* __restrict__ W,
                                           int K, int N, int NC,
                                           float* __restrict__ dst, float* sA) {
    int blk = blockIdx.x, tid = threadIdx.x;
    int nblocks = NC * ((K / KC) / 2);
    if (blk < nblocks) {
        int nc = blk % NC;
        int kpair = blk / NC;
        int sub = tid >> 8;
        int n = nc * 256 + (tid & 255);
        int kch = kpair * 2 + sub;

        const float* Wp = W + (size_t)(kch * KC) * N + n;
        float wreg[KC];
        #pragma unroll
        for (int kk = 0; kk < KC; kk++) wreg[kk] = Wp[(size_t)kk * N];

        for (int i = tid; i < 8 * KC; i += NT) {
            int s2 = i / (4 * KC);
            int rem = i - s2 * 4 * KC;
            int b = rem / KC, kk = rem - b * KC;
            int kg = (kpair * 2 + s2) * KC + kk;
            float v = 0.f;
            if (srcXpart) {
                #pragma unroll 8
                for (int c = 0; c < 32; c++)
                    v += g_xpart[(size_t)(b * 32 + c) * DD + kg];
            } else {
                #pragma unroll 8
                for (int kc = 0; kc < srcKCH; kc++)
                    v += src[((size_t)kc * BB + b) * K + kg];
            }
            if (bias) v += bias[kg];
            if (act) v = 0.5f * v * (1.0f + erff(v * 0.70710678118654752f));
            sA[(s2 * 4 + b) * KC + kk] = v;
        }
        __syncthreads();

        const float* a = sA + sub * 4 * KC;
        float a0 = 0.f, a1 = 0.f, a2 = 0.f, a3 = 0.f;
        #pragma unroll
        for (int kk = 0; kk < KC; kk++) {
            float w = wreg[kk];
            a0 += a[kk] * w;
            a1 += a[KC + kk] * w;
            a2 += a[2 * KC + kk] * w;
            a3 += a[3 * KC + kk] * w;
        }
        size_t base = (size_t)kch * BB * N + n;
        dst[base]         = a0;
        dst[base + N]     = a1;
        dst[base + 2 * N] = a2;
        dst[base + 3 * N] = a3;
        __syncthreads();
    }
}

// ============ persistent kernel: embeddings ... ln_f ... logits ==============
__global__ __launch_bounds__(NT, 1)
void k_main(const int* __restrict__ idx, const float* __restrict__ wte,
            const float* __restrict__ wpe, const float* __restrict__ lnw,
            const float* __restrict__ kw,  const float* __restrict__ kb,
            const float* __restrict__ vw,  const float* __restrict__ vb,
            const float* __restrict__ fcw, const float* __restrict__ pw) {
    __shared__ __align__(16) float sm[BB * DD];
    __shared__ int smi[32];
    int blk = blockIdx.x, tid = threadIdx.x;
    int lane = tid & 31, wid = tid >> 5;
    int gw = blk * (NT / 32) + wid;

    // S0: kwm[i] = mean_d kw0[i,d]; kbm = mean(kb0)
    for (int i = gw; i < DD; i += NWARP) {
        const float* row = kw + (size_t)i * DD;
        float s = 0.f;
        #pragma unroll
        for (int jj = 0; jj < DD / 32; jj++) s += row[lane + jj * 32];
        s = warp_sum(s);
        if (lane == 0) g_kwm[i] = s * (1.0f / DD);
    }
    if (gw == NWARP - 1) {
        float s = 0.f;
        #pragma unroll
        for (int jj = 0; jj < DD / 32; jj++) s += kb[lane + jj * 32];
        s = warp_sum(s);
        if (lane == 0) g_kbm = s * (1.0f / DD);
    }
    gsync();

    // S1: k_mean[b,t] = (wte[idx]+wpe[t]) . kwm + kbm
    for (int i = tid; i < DD; i += NT) sm[i] = g_kwm[i];
    __syncthreads();
    for (int tok = gw; tok < BB * TT; tok += NWARP) {
        int t = tok & (TT - 1);
        const float* e = wte + (size_t)idx[tok] * DD;
        const float* p = wpe + (size_t)t * DD;
        float s = 0.f;
        #pragma unroll
        for (int jj = 0; jj < DD / 32; jj++) {
            int j = lane + jj * 32;
            s += (e[j] + p[j]) * sm[j];
        }
        s = warp_sum(s);
        if (lane == 0) g_kmean[tok] = s + g_kbm;
    }
    gsync();

    // S2: softmax over T of cos(k_mean), per batch
    if (blk < BB) {
        float v0 = cosf(g_kmean[blk * TT + tid]);
        float v1 = cosf(g_kmean[blk * TT + tid + 512]);
        sm[tid] = fmaxf(v0, v1); __syncthreads();
        for (int o = 256; o; o >>= 1) { if (tid < o) sm[tid] = fmaxf(sm[tid], sm[tid + o]); __syncthreads(); }
        float mx = sm[0]; __syncthreads();
        float e0 = expf(v0 - mx), e1 = expf(v1 - mx);
        sm[tid] = e0 + e1; __syncthreads();
        for (int o = 256; o; o >>= 1) { if (tid < o) sm[tid] += sm[tid + o]; __syncthreads(); }
        float inv = 1.0f / sm[0];
        g_w[blk * TT + tid]       = e0 * inv;
        g_w[blk * TT + tid + 512] = e1 * inv;
    }
    gsync();

    // S3: xbar partials
    if (blk < 128) {
        int b = blk >> 5, c = blk & 31;
        if (tid < 32) {
            int t = c * 32 + tid;
            sm[tid]  = g_w[b * TT + t];
            smi[tid] = idx[b * TT + t];
        }
        __syncthreads();
        for (int d = tid; d < DD; d += NT) {
            float acc = 0.f;
            #pragma unroll 8
            for (int j = 0; j < 32; j++) {
                int t = c * 32 + j;
                acc += sm[j] * (wte[(size_t)smi[j] * DD + d] + wpe[(size_t)t * DD + d]);
            }
            g_xpart[(size_t)blk * DD + d] = acc;
        }
    }
    gsync();

    // 4 layers, split-K partials ping-pong; reductions fused into consumers.
    float* P[2] = {g_pA, g_pB};
    int xb = -1;
    for (int l = 0; l < LL; l++) {
        const float* vwl  = vw  + (size_t)l * DD * DD;
        const float* vbl  = vb  + (size_t)l * DD;
        const float* fcwl = fcw + (size_t)l * DD * DFF;
        const float* pwl  = pw  + (size_t)l * DFF * DD;

        float* d0 = (xb == 1) ? P[0] : ((xb == 0) ? P[1] : P[0]);
        float* d1 = (d0 == P[0]) ? P[1] : P[0];
        const float* xsrc = (xb < 0) ? nullptr : P[xb];

        gemm_stage<8>(xb < 0, xsrc, 96, nullptr, 0, vwl, DD, DD, 3, d0, sm);
        gsync();
        gemm_stage<32>(0, d0, 96, vbl, 0, fcwl, DD, DFF, 12, d1, sm);
        gsync();
        gemm_stage<32>(0, d1, 24, nullptr, 1, pwl, DFF, DD, 3, d0, sm);
        gsync();
        xb = (d0 == P[0]) ? 0 : 1;
    }

    // ln_f (blocks 0..3), reducing final partials
    if (blk < BB) {
        const float* Px = P[xb];
        float v0 = 0.f, v1 = 0.f;
        #pragma unroll 8
        for (int kc = 0; kc < 96; kc++)
            v0 += Px[((size_t)kc * BB + blk) * DD + tid];
        if (tid < 256) {
            #pragma unroll 8
            for (int kc = 0; kc < 96; kc++)
                v1 += Px[((size_t)kc * BB + blk) * DD + tid + 512];
        }
        sm[tid] = v0 + v1; __syncthreads();
        for (int o = 256; o; o >>= 1) { if (tid < o) sm[tid] += sm[tid + o]; __syncthreads(); }
        float mu = sm[0] * (1.0f / DD); __syncthreads();
        float d0 = v0 - mu, d1 = (tid < 256) ? (v1 - mu) : 0.f;
        sm[tid] = d0 * d0 + ((tid < 256) ? d1 * d1 : 0.f); __syncthreads();
        for (int o = 256; o; o >>= 1) { if (tid < o) sm[tid] += sm[tid + o]; __syncthreads(); }
        float rstd = rsqrtf(sm[0] * (1.0f / DD) + 1e-5f);
        g_xn[blk * DD + tid] = d0 * rstd * lnw[tid];
        if (tid < 256) g_xn[blk * DD + tid + 512] = d1 * rstd * lnw[tid + 512];
    }
    gsync();

    // logits: g_logits[b,v] = xn[b,:].wte[v,:]  (warp per vocab row)
    {
        float4* sxn4 = (float4*)sm;
        for (int i = tid; i < BB * DD / 4; i += NT)
            sxn4[i] = ((const float4*)g_xn)[i];
        __syncthreads();
        for (int v = gw; v < VV; v += NWARP) {
            const float4* wr = (const float4*)(wte + (size_t)v * DD);
            float a0 = 0.f, a1 = 0.f, a2 = 0.f, a3 = 0.f;
            #pragma unroll
            for (int jj = 0; jj < DD / 128; jj++) {
                int j = lane + jj * 32;
                float4 w = wr[j];
                float4 x0 = sxn4[j];
                float4 x1 = sxn4[192 + j];
                float4 x2 = sxn4[384 + j];
                float4 x3 = sxn4[576 + j];
                a0 += w.x * x0.x + w.y * x0.y + w.z * x0.z + w.w * x0.w;
                a1 += w.x * x1.x + w.y * x1.y + w.z * x1.z + w.w * x1.w;
                a2 += w.x * x2.x + w.y * x2.y + w.z * x2.z + w.w * x2.w;
                a3 += w.x * x3.x + w.y * x3.y + w.z * x3.z + w.w * x3.w;
            }
            a0 = warp_sum(a0); a1 = warp_sum(a1); a2 = warp_sum(a2); a3 = warp_sum(a3);
            if (lane == 0) {
                g_logits[v]               = a0;
                g_logits[LSTRIDE + v]     = a1;
                g_logits[2 * LSTRIDE + v] = a2;
                g_logits[3 * LSTRIDE + v] = a3;
            }
        }
    }
}

// =============== broadcast: high-occupancy windowed streaming ================
// Block = (batch, column window of WIN, 64-row group). Window cached in smem.
// Warp w handles rows r == w (mod 8) -> alignment class (r mod 4) constant per
// warp -> unpredicated aligned STG.128 stream fed by conflict-free LDS.128.
__global__ __launch_bounds__(256)
void k_bcast(float* __restrict__ out) {
    __shared__ __align__(16) float smf[WIN + 4];
    float4* sm4 = (float4*)smf;
    int tid = threadIdx.x, warp = tid >> 5, lane = tid & 31;

    int blk = blockIdx.x;
    int b   = blk & 3;
    int rest = blk >> 2;
    int win = rest % NWIN;
    int rg  = rest / NWIN;

    int w0 = win * WIN;
    int wlen = VV - w0; if (wlen > WIN) wlen = WIN;

    const float* src = g_logits + (size_t)b * LSTRIDE + w0;
    for (int i = tid; i < wlen; i += 256) smf[i] = src[i];
    __syncthreads();

    int a = warp & 3;                    // (r + w0) & 3, w0 % 4 == 0
    int head = (4 - a) & 3;
    int nvec = (wlen - head) >> 2;
    int tail = wlen - head - 4 * nvec;

    for (int r = rg * 64 + warp; r < rg * 64 + 64; r += 8) {
        float* dst = out + (size_t)(b * TT + r) * VV + w0;
        if (lane < head) dst[lane] = smf[lane];
        float4* d4 = (float4*)(dst + head);
        if (a == 0) {
            for (int i = lane; i < nvec; i += 32) __stcs(d4 + i, sm4[i]);
        } else if (a == 3) {             // head = 1
            for (int i = lane; i < nvec; i += 32) {
                float4 x = sm4[i], y = sm4[i + 1];
                __stcs(d4 + i, make_float4(x.y, x.z, x.w, y.x));
            }
        } else if (a == 2) {             // head = 2
            for (int i = lane; i < nvec; i += 32) {
                float4 x = sm4[i], y = sm4[i + 1];
                __stcs(d4 + i, make_float4(x.z, x.w, y.x, y.y));
            }
        } else {                         // a == 1, head = 3
            for (int i = lane; i < nvec; i += 32) {
                float4 x = sm4[i], y = sm4[i + 1];
                __stcs(d4 + i, make_float4(x.w, y.x, y.y, y.z));
            }
        }
        if (lane < tail) dst[head + 4 * nvec + lane] = smf[head + 4 * nvec + lane];
    }
}

// ---------------- launch ------------------------------------------------------
extern "C" void kernel_launch(void* const* d_in, const int* in_sizes, int n_in,
                              void* d_out, int out_size) {
    const int*   idx = (const int*)  d_in[0];
    const float* wte = (const float*)d_in[1];
    const float* wpe = (const float*)d_in[2];
    const float* lnw = (const float*)d_in[3];
    // d_in[4]=qw, d_in[5]=qb : dead (scores independent of Q)
    const float* kw  = (const float*)d_in[6];
    const float* kb  = (const float*)d_in[7];
    const float* vw  = (const float*)d_in[8];
    const float* vb  = (const float*)d_in[9];
    const float* fcw = (const float*)d_in[10];
    const float* pw  = (const float*)d_in[11];
    float* out = (float*)d_out;

    k_main<<<NB, NT>>>(idx, wte, wpe, lnw, kw, kb, vw, vb, fcw, pw);
    k_bcast<<<BB * NWIN * RG, 256>>>(out);
}

// round 6
// speedup vs baseline: 1.2885x; 1.0712x over previous
#include <cuda_runtime.h>
#include <cstdint>

#define BB 4
#define TT 1024
#define DD 768
#define LL 4
#define DFF 3072
#define VV 50257
#define NB 148
#define NT 512
#define NWARP (NB * (NT / 32))   // 2368 warps (k_main)
#define LSTRIDE 50260            // VV padded to multiple of 4
#define WIN 2048                 // broadcast column window (floats)
#define NWIN 25                  // ceil(VV / WIN)
#define RG 32                    // row groups (32 rows each)
#define XCH 48                   // split-K chunks held by x-partials

// ---------------- scratch (static __device__, no allocations) ----------------
__device__ float g_kwm[DD];
__device__ float g_kbm;
__device__ float g_kmean[BB * TT];
__device__ float g_w[BB * TT];
__device__ float g_xpart[BB * 32 * DD];
__device__ float g_pA[96 * BB * DD];
__device__ float g_pB[96 * BB * DD];
__device__ __align__(16) float g_xn[BB * DD];
__device__ __align__(16) float g_logits[BB * LSTRIDE];

__device__ unsigned g_arrive;
__device__ unsigned g_phase;

__device__ __forceinline__ float warp_sum(float v) {
    #pragma unroll
    for (int o = 16; o; o >>= 1) v += __shfl_xor_sync(0xffffffffu, v, o);
    return v;
}

// grid-wide barrier: all NB blocks co-resident (1 block/SM).
__device__ __forceinline__ void gsync() {
    __syncthreads();
    if (threadIdx.x == 0) {
        volatile unsigned* ph = &g_phase;
        unsigned gen = *ph;
        __threadfence();
        if (atomicAdd(&g_arrive, 1u) == NB - 1) {
            g_arrive = 0;
            __threadfence();
            *ph = gen + 1;
        } else {
            while (*ph == gen) { }
        }
        __threadfence();
    }
    __syncthreads();
}

// ---- skinny GEMM stage; W prefetched to registers BEFORE input reduction ----
template<int KC>
__device__ __forceinline__ void gemm_stage(int srcXpart, const float* __restrict__ src,
                                           int srcKCH, const float* __restrict__ bias,
                                           int act, const float* __restrict__ W,
                                           int K, int N, int NC,
                                           float* __restrict__ dst, float* sA) {
    int blk = blockIdx.x, tid = threadIdx.x;
    int nblocks = NC * ((K / KC) / 2);
    if (blk < nblocks) {
        int nc = blk % NC;
        int kpair = blk / NC;
        int sub = tid >> 8;
        int n = nc * 256 + (tid & 255);
        int kch = kpair * 2 + sub;

        const float* Wp = W + (size_t)(kch * KC) * N + n;
        float wreg[KC];
        #pragma unroll
        for (int kk = 0; kk < KC; kk++) wreg[kk] = Wp[(size_t)kk * N];

        for (int i = tid; i < 8 * KC; i += NT) {
            int s2 = i / (4 * KC);
            int rem = i - s2 * 4 * KC;
            int b = rem / KC, kk = rem - b * KC;
            int kg = (kpair * 2 + s2) * KC + kk;
            float v = 0.f;
            if (srcXpart) {
                #pragma unroll 8
                for (int c = 0; c < 32; c++)
                    v += g_xpart[(size_t)(b * 32 + c) * DD + kg];
            } else {
                #pragma unroll 8
                for (int kc = 0; kc < srcKCH; kc++)
                    v += src[((size_t)kc * BB + b) * K + kg];
            }
            if (bias) v += bias[kg];
            if (act) v = 0.5f * v * (1.0f + erff(v * 0.70710678118654752f));
            sA[(s2 * 4 + b) * KC + kk] = v;
        }
        __syncthreads();

        const float* a = sA + sub * 4 * KC;
        float a0 = 0.f, a1 = 0.f, a2 = 0.f, a3 = 0.f;
        #pragma unroll
        for (int kk = 0; kk < KC; kk++) {
            float w = wreg[kk];
            a0 += a[kk] * w;
            a1 += a[KC + kk] * w;
            a2 += a[2 * KC + kk] * w;
            a3 += a[3 * KC + kk] * w;
        }
        size_t base = (size_t)kch * BB * N + n;
        dst[base]         = a0;
        dst[base + N]     = a1;
        dst[base + 2 * N] = a2;
        dst[base + 3 * N] = a3;
        __syncthreads();
    }
}

// ============ persistent kernel: embeddings ... ln_f ... logits ==============
__global__ __launch_bounds__(NT, 1)
void k_main(const int* __restrict__ idx, const float* __restrict__ wte,
            const float* __restrict__ wpe, const float* __restrict__ lnw,
            const float* __restrict__ kw,  const float* __restrict__ kb,
            const float* __restrict__ vw,  const float* __restrict__ vb,
            const float* __restrict__ fcw, const float* __restrict__ pw) {
    __shared__ __align__(16) float sm[BB * DD];
    __shared__ int smi[32];
    int blk = blockIdx.x, tid = threadIdx.x;
    int lane = tid & 31, wid = tid >> 5;
    int gw = blk * (NT / 32) + wid;

    // S0: kwm[i] = mean_d kw0[i,d]; kbm = mean(kb0)
    for (int i = gw; i < DD; i += NWARP) {
        const float* row = kw + (size_t)i * DD;
        float s = 0.f;
        #pragma unroll
        for (int jj = 0; jj < DD / 32; jj++) s += row[lane + jj * 32];
        s = warp_sum(s);
        if (lane == 0) g_kwm[i] = s * (1.0f / DD);
    }
    if (gw == NWARP - 1) {
        float s = 0.f;
        #pragma unroll
        for (int jj = 0; jj < DD / 32; jj++) s += kb[lane + jj * 32];
        s = warp_sum(s);
        if (lane == 0) g_kbm = s * (1.0f / DD);
    }
    gsync();

    // S1: k_mean[b,t] = (wte[idx]+wpe[t]) . kwm + kbm
    for (int i = tid; i < DD; i += NT) sm[i] = g_kwm[i];
    __syncthreads();
    for (int tok = gw; tok < BB * TT; tok += NWARP) {
        int t = tok & (TT - 1);
        const float* e = wte + (size_t)idx[tok] * DD;
        const float* p = wpe + (size_t)t * DD;
        float s = 0.f;
        #pragma unroll
        for (int jj = 0; jj < DD / 32; jj++) {
            int j = lane + jj * 32;
            s += (e[j] + p[j]) * sm[j];
        }
        s = warp_sum(s);
        if (lane == 0) g_kmean[tok] = s + g_kbm;
    }
    gsync();

    // S2: softmax over T of cos(k_mean), per batch
    if (blk < BB) {
        float v0 = cosf(g_kmean[blk * TT + tid]);
        float v1 = cosf(g_kmean[blk * TT + tid + 512]);
        sm[tid] = fmaxf(v0, v1); __syncthreads();
        for (int o = 256; o; o >>= 1) { if (tid < o) sm[tid] = fmaxf(sm[tid], sm[tid + o]); __syncthreads(); }
        float mx = sm[0]; __syncthreads();
        float e0 = expf(v0 - mx), e1 = expf(v1 - mx);
        sm[tid] = e0 + e1; __syncthreads();
        for (int o = 256; o; o >>= 1) { if (tid < o) sm[tid] += sm[tid + o]; __syncthreads(); }
        float inv = 1.0f / sm[0];
        g_w[blk * TT + tid]       = e0 * inv;
        g_w[blk * TT + tid + 512] = e1 * inv;
    }
    gsync();

    // S3: xbar partials
    if (blk < 128) {
        int b = blk >> 5, c = blk & 31;
        if (tid < 32) {
            int t = c * 32 + tid;
            sm[tid]  = g_w[b * TT + t];
            smi[tid] = idx[b * TT + t];
        }
        __syncthreads();
        for (int d = tid; d < DD; d += NT) {
            float acc = 0.f;
            #pragma unroll 8
            for (int j = 0; j < 32; j++) {
                int t = c * 32 + j;
                acc += sm[j] * (wte[(size_t)smi[j] * DD + d] + wpe[(size_t)t * DD + d]);
            }
            g_xpart[(size_t)blk * DD + d] = acc;
        }
    }
    gsync();

    // 4 layers, split-K partials ping-pong; reductions fused into consumers.
    // Chunk counts: vw KC=16 -> 48 chunks; fcw KC=32 -> 24; pw KC=64 -> 48.
    float* P[2] = {g_pA, g_pB};
    int xb = -1;
    for (int l = 0; l < LL; l++) {
        const float* vwl  = vw  + (size_t)l * DD * DD;
        const float* vbl  = vb  + (size_t)l * DD;
        const float* fcwl = fcw + (size_t)l * DD * DFF;
        const float* pwl  = pw  + (size_t)l * DFF * DD;

        float* d0 = (xb == 1) ? P[0] : ((xb == 0) ? P[1] : P[0]);
        float* d1 = (d0 == P[0]) ? P[1] : P[0];
        const float* xsrc = (xb < 0) ? nullptr : P[xb];

        gemm_stage<16>(xb < 0, xsrc, XCH, nullptr, 0, vwl, DD, DD, 3, d0, sm);
        gsync();
        gemm_stage<32>(0, d0, 48, vbl, 0, fcwl, DD, DFF, 12, d1, sm);
        gsync();
        gemm_stage<64>(0, d1, 24, nullptr, 1, pwl, DFF, DD, 3, d0, sm);
        gsync();
        xb = (d0 == P[0]) ? 0 : 1;
    }

    // ln_f (blocks 0..3), reducing final partials (XCH chunks)
    if (blk < BB) {
        const float* Px = P[xb];
        float v0 = 0.f, v1 = 0.f;
        #pragma unroll 8
        for (int kc = 0; kc < XCH; kc++)
            v0 += Px[((size_t)kc * BB + blk) * DD + tid];
        if (tid < 256) {
            #pragma unroll 8
            for (int kc = 0; kc < XCH; kc++)
                v1 += Px[((size_t)kc * BB + blk) * DD + tid + 512];
        }
        sm[tid] = v0 + v1; __syncthreads();
        for (int o = 256; o; o >>= 1) { if (tid < o) sm[tid] += sm[tid + o]; __syncthreads(); }
        float mu = sm[0] * (1.0f / DD); __syncthreads();
        float d0 = v0 - mu, d1 = (tid < 256) ? (v1 - mu) : 0.f;
        sm[tid] = d0 * d0 + ((tid < 256) ? d1 * d1 : 0.f); __syncthreads();
        for (int o = 256; o; o >>= 1) { if (tid < o) sm[tid] += sm[tid + o]; __syncthreads(); }
        float rstd = rsqrtf(sm[0] * (1.0f / DD) + 1e-5f);
        g_xn[blk * DD + tid] = d0 * rstd * lnw[tid];
        if (tid < 256) g_xn[blk * DD + tid + 512] = d1 * rstd * lnw[tid + 512];
    }
    gsync();

    // logits: g_logits[b,v] = xn[b,:].wte[v,:]  (warp per vocab row)
    {
        float4* sxn4 = (float4*)sm;
        for (int i = tid; i < BB * DD / 4; i += NT)
            sxn4[i] = ((const float4*)g_xn)[i];
        __syncthreads();
        for (int v = gw; v < VV; v += NWARP) {
            const float4* wr = (const float4*)(wte + (size_t)v * DD);
            float a0 = 0.f, a1 = 0.f, a2 = 0.f, a3 = 0.f;
            #pragma unroll
            for (int jj = 0; jj < DD / 128; jj++) {
                int j = lane + jj * 32;
                float4 w = wr[j];
                float4 x0 = sxn4[j];
                float4 x1 = sxn4[192 + j];
                float4 x2 = sxn4[384 + j];
                float4 x3 = sxn4[576 + j];
                a0 += w.x * x0.x + w.y * x0.y + w.z * x0.z + w.w * x0.w;
                a1 += w.x * x1.x + w.y * x1.y + w.z * x1.z + w.w * x1.w;
                a2 += w.x * x2.x + w.y * x2.y + w.z * x2.z + w.w * x2.w;
                a3 += w.x * x3.x + w.y * x3.y + w.z * x3.z + w.w * x3.w;
            }
            a0 = warp_sum(a0); a1 = warp_sum(a1); a2 = warp_sum(a2); a3 = warp_sum(a3);
            if (lane == 0) {
                g_logits[v]               = a0;
                g_logits[LSTRIDE + v]     = a1;
                g_logits[2 * LSTRIDE + v] = a2;
                g_logits[3 * LSTRIDE + v] = a3;
            }
        }
    }
}

// =============== broadcast: high-occupancy windowed streaming ================
// Block = (batch, 2048-col window, 32-row group). Window cached in 8KB smem.
// Per row: alignment class (r mod 4) -> unpredicated aligned STG.128 stream
// fed by conflict-free LDS.128 blends. Grid 3200 -> ~8 blocks/SM resident.
__global__ __launch_bounds__(256)
void k_bcast(float* __restrict__ out) {
    __shared__ __align__(16) float smf[WIN + 4];
    float4* sm4 = (float4*)smf;
    int tid = threadIdx.x, warp = tid >> 5, lane = tid & 31;

    int blk = blockIdx.x;
    int b   = blk & 3;
    int rest = blk >> 2;
    int win = rest % NWIN;
    int rg  = rest / NWIN;

    int w0 = win * WIN;
    int wlen = VV - w0; if (wlen > WIN) wlen = WIN;

    const float* src = g_logits + (size_t)b * LSTRIDE + w0;
    for (int i = tid; i < wlen; i += 256) smf[i] = src[i];
    __syncthreads();

    #pragma unroll
    for (int rr = 0; rr < 4; rr++) {
        int r = rg * 32 + rr * 8 + warp;
        int a = r & 3;                     // w0 % 4 == 0
        int head = (4 - a) & 3;
        int nvec = (wlen - head) >> 2;
        int tail = wlen - head - 4 * nvec;

        float* dst = out + (size_t)(b * TT + r) * VV + w0;
        if (lane < head) dst[lane] = smf[lane];
        float4* d4 = (float4*)(dst + head);
        if (a == 0) {
            for (int i = lane; i < nvec; i += 32) __stcs(d4 + i, sm4[i]);
        } else if (a == 3) {               // head = 1
            for (int i = lane; i < nvec; i += 32) {
                float4 x = sm4[i], y = sm4[i + 1];
                __stcs(d4 + i, make_float4(x.y, x.z, x.w, y.x));
            }
        } else if (a == 2) {               // head = 2
            for (int i = lane; i < nvec; i += 32) {
                float4 x = sm4[i], y = sm4[i + 1];
                __stcs(d4 + i, make_float4(x.z, x.w, y.x, y.y));
            }
        } else {                           // a == 1, head = 3
            for (int i = lane; i < nvec; i += 32) {
                float4 x = sm4[i], y = sm4[i + 1];
                __stcs(d4 + i, make_float4(x.w, y.x, y.y, y.z));
            }
        }
        if (lane < tail) dst[head + 4 * nvec + lane] = smf[head + 4 * nvec + lane];
    }
}

// ---------------- launch ------------------------------------------------------
extern "C" void kernel_launch(void* const* d_in, const int* in_sizes, int n_in,
                              void* d_out, int out_size) {
    const int*   idx = (const int*)  d_in[0];
    const float* wte = (const float*)d_in[1];
    const float* wpe = (const float*)d_in[2];
    const float* lnw = (const float*)d_in[3];
    // d_in[4]=qw, d_in[5]=qb : dead (scores independent of Q)
    const float* kw  = (const float*)d_in[6];
    const float* kb  = (const float*)d_in[7];
    const float* vw  = (const float*)d_in[8];
    const float* vb  = (const float*)d_in[9];
    const float* fcw = (const float*)d_in[10];
    const float* pw  = (const float*)d_in[11];
    float* out = (float*)d_out;

    k_main<<<NB, NT>>>(idx, wte, wpe, lnw, kw, kb, vw, vb, fcw, pw);
    k_bcast<<<BB * NWIN * RG, 256>>>(out);
}

// round 8
// speedup vs baseline: 1.3554x; 1.0519x over previous
#include <cuda_runtime.h>
#include <cstdint>

#define BB 4
#define TT 1024
#define DD 768
#define LL 4
#define DFF 3072
#define VV 50257
#define NB 148
#define NT 512
#define NWARP (NB * (NT / 32))   // 2368 warps (k_main)
#define LSTRIDE 50260            // VV padded to multiple of 4
#define WIN 2048                 // broadcast column window (floats)
#define NWIN 25                  // ceil(VV / WIN)
#define RG 32                    // row groups (32 rows each)
#define XCH 48                   // split-K chunks held by x-partials

// ---------------- scratch (static __device__, no allocations) ----------------
__device__ float g_kwm[DD];
__device__ float g_kbm;
__device__ float g_e[BB * TT];          // exp(cos(k_mean)), unnormalized
__device__ float g_Z[BB];               // softmax denominators
__device__ float g_xpart[BB * 32 * DD];
__device__ float g_pA[96 * BB * DD];
__device__ float g_pB[96 * BB * DD];
__device__ __align__(16) float g_xn[BB * DD];
__device__ __align__(16) float g_logits[BB * LSTRIDE];

__device__ unsigned g_arrive;           // monotonic across launches
__device__ unsigned g_phase;            // monotonic generation counter

__device__ __forceinline__ float warp_sum(float v) {
    #pragma unroll
    for (int o = 16; o; o >>= 1) v += __shfl_xor_sync(0xffffffffu, v, o);
    return v;
}

// Lightweight grid barrier (148 co-resident blocks). Mutable scratch uses
// __ldcg/__stcg (L2-only), so no L1 invalidation needed; release/acquire
// scoped atomics provide the happens-before edge.
// State is monotonic ACROSS launches: gen must be seeded from g_phase at
// kernel entry (see k_main) so graph replays continue the sequence.
__device__ __forceinline__ void gsync(unsigned& gen) {
    __syncthreads();
    if (threadIdx.x == 0) {
        gen += NB;
        unsigned old;
        asm volatile("atom.acq_rel.gpu.add.u32 %0, [%1], 1;"
                     : "=r"(old) : "l"(&g_arrive) : "memory");
        if (old == gen - 1) {
            asm volatile("st.release.gpu.u32 [%0], %1;"
                         :: "l"(&g_phase), "r"(gen) : "memory");
        } else {
            unsigned cur;
            do {
                asm volatile("ld.acquire.gpu.u32 %0, [%1];"
                             : "=r"(cur) : "l"(&g_phase) : "memory");
            } while (cur < gen);
        }
    }
    __syncthreads();
}

// ---- skinny GEMM stage; W prefetched to registers BEFORE input reduction ----
// Scratch I/O is all L2 (ldcg/stcg). First layer divides by softmax Z here.
template<int KC>
__device__ __forceinline__ void gemm_stage(int srcXpart, const float* __restrict__ src,
                                           int srcKCH, const float* __restrict__ bias,
                                           int act, const float* __restrict__ W,
                                           int K, int N, int NC,
                                           float* __restrict__ dst, float* sA) {
    int blk = blockIdx.x, tid = threadIdx.x;
    int nblocks = NC * ((K / KC) / 2);
    if (blk < nblocks) {
        int nc = blk % NC;
        int kpair = blk / NC;
        int sub = tid >> 8;
        int n = nc * 256 + (tid & 255);
        int kch = kpair * 2 + sub;

        const float* Wp = W + (size_t)(kch * KC) * N + n;
        float wreg[KC];
        #pragma unroll
        for (int kk = 0; kk < KC; kk++) wreg[kk] = Wp[(size_t)kk * N];

        float rz[BB];
        if (srcXpart) {
            #pragma unroll
            for (int b = 0; b < BB; b++) rz[b] = 1.0f / __ldcg(&g_Z[b]);
        }

        for (int i = tid; i < 8 * KC; i += NT) {
            int s2 = i / (4 * KC);
            int rem = i - s2 * 4 * KC;
            int b = rem / KC, kk = rem - b * KC;
            int kg = (kpair * 2 + s2) * KC + kk;
            float v = 0.f;
            if (srcXpart) {
                #pragma unroll 8
                for (int c = 0; c < 32; c++)
                    v += __ldcg(&g_xpart[(size_t)(b * 32 + c) * DD + kg]);
                v *= rz[b];
            } else {
                #pragma unroll 8
                for (int kc = 0; kc < srcKCH; kc++)
                    v += __ldcg(&src[((size_t)kc * BB + b) * K + kg]);
            }
            if (bias) v += bias[kg];
            if (act) v = 0.5f * v * (1.0f + erff(v * 0.70710678118654752f));
            sA[(s2 * 4 + b) * KC + kk] = v;
        }
        __syncthreads();

        const float* a = sA + sub * 4 * KC;
        float a0 = 0.f, a1 = 0.f, a2 = 0.f, a3 = 0.f;
        #pragma unroll
        for (int kk = 0; kk < KC; kk++) {
            float w = wreg[kk];
            a0 += a[kk] * w;
            a1 += a[KC + kk] * w;
            a2 += a[2 * KC + kk] * w;
            a3 += a[3 * KC + kk] * w;
        }
        size_t base = (size_t)kch * BB * N + n;
        __stcg(&dst[base],         a0);
        __stcg(&dst[base + N],     a1);
        __stcg(&dst[base + 2 * N], a2);
        __stcg(&dst[base + 3 * N], a3);
    }
}

// ============ persistent kernel: embeddings ... ln_f ... logits ==============
__global__ __launch_bounds__(NT, 1)
void k_main(const int* __restrict__ idx, const float* __restrict__ wte,
            const float* __restrict__ wpe, const float* __restrict__ lnw,
            const float* __restrict__ kw,  const float* __restrict__ kb,
            const float* __restrict__ vw,  const float* __restrict__ vb,
            const float* __restrict__ fcw, const float* __restrict__ pw) {
    __shared__ __align__(16) float sm[BB * DD];
    __shared__ int smi[32];
    int blk = blockIdx.x, tid = threadIdx.x;
    int lane = tid & 31, wid = tid >> 5;
    int gw = blk * (NT / 32) + wid;

    // Seed barrier generation from the persistent counter: previous launch
    // fully retired, so g_phase is stable and identical for all blocks.
    unsigned gen;
    asm volatile("ld.acquire.gpu.u32 %0, [%1];" : "=r"(gen) : "l"(&g_phase) : "memory");

    // S0: kwm[i] = mean_d kw0[i,d]; kbm = mean(kb0)
    for (int i = gw; i < DD; i += NWARP) {
        const float* row = kw + (size_t)i * DD;
        float s = 0.f;
        #pragma unroll
        for (int jj = 0; jj < DD / 32; jj++) s += row[lane + jj * 32];
        s = warp_sum(s);
        if (lane == 0) __stcg(&g_kwm[i], s * (1.0f / DD));
    }
    if (gw == NWARP - 1) {
        float s = 0.f;
        #pragma unroll
        for (int jj = 0; jj < DD / 32; jj++) s += kb[lane + jj * 32];
        s = warp_sum(s);
        if (lane == 0) __stcg(&g_kbm, s * (1.0f / DD));
    }
    gsync(gen);

    // S1: e[b,t] = exp(cos((wte[idx]+wpe[t]).kwm + kbm))  (cos bounded -> no max)
    for (int i = tid; i < DD; i += NT) sm[i] = __ldcg(&g_kwm[i]);
    __syncthreads();
    {
        float kbm = __ldcg(&g_kbm);
        for (int tok = gw; tok < BB * TT; tok += NWARP) {
            int t = tok & (TT - 1);
            const float* e = wte + (size_t)idx[tok] * DD;
            const float* p = wpe + (size_t)t * DD;
            float s = 0.f;
            #pragma unroll
            for (int jj = 0; jj < DD / 32; jj++) {
                int j = lane + jj * 32;
                s += (e[j] + p[j]) * sm[j];
            }
            s = warp_sum(s);
            if (lane == 0) __stcg(&g_e[tok], expf(cosf(s + kbm)));
        }
    }
    gsync(gen);

    // S2 (merged): blocks 0-3 compute Z[b]; blocks 4-131 compute xbar partials
    if (blk < BB) {
        float v0 = __ldcg(&g_e[blk * TT + tid]);
        float v1 = __ldcg(&g_e[blk * TT + tid + 512]);
        sm[tid] = v0 + v1; __syncthreads();
        for (int o = 256; o; o >>= 1) { if (tid < o) sm[tid] += sm[tid + o]; __syncthreads(); }
        if (tid == 0) __stcg(&g_Z[blk], sm[0]);
    } else if (blk < 132) {
        int b = (blk - 4) >> 5, c = (blk - 4) & 31;
        if (tid < 32) {
            int t = c * 32 + tid;
            sm[tid]  = __ldcg(&g_e[b * TT + t]);
            smi[tid] = idx[b * TT + t];
        }
        __syncthreads();
        for (int d = tid; d < DD; d += NT) {
            float acc = 0.f;
            #pragma unroll 8
            for (int j = 0; j < 32; j++) {
                int t = c * 32 + j;
                acc += sm[j] * (wte[(size_t)smi[j] * DD + d] + wpe[(size_t)t * DD + d]);
            }
            __stcg(&g_xpart[(size_t)((b * 32 + c)) * DD + d], acc);
        }
    }
    gsync(gen);

    // 4 layers, split-K partials ping-pong; reductions fused into consumers.
    float* P[2] = {g_pA, g_pB};
    int xb = -1;
    for (int l = 0; l < LL; l++) {
        const float* vwl  = vw  + (size_t)l * DD * DD;
        const float* vbl  = vb  + (size_t)l * DD;
        const float* fcwl = fcw + (size_t)l * DD * DFF;
        const float* pwl  = pw  + (size_t)l * DFF * DD;

        float* d0 = (xb == 1) ? P[0] : ((xb == 0) ? P[1] : P[0]);
        float* d1 = (d0 == P[0]) ? P[1] : P[0];
        const float* xsrc = (xb < 0) ? nullptr : P[xb];

        gemm_stage<16>(xb < 0, xsrc, XCH, nullptr, 0, vwl, DD, DD, 3, d0, sm);
        gsync(gen);
        gemm_stage<32>(0, d0, 48, vbl, 0, fcwl, DD, DFF, 12, d1, sm);
        gsync(gen);
        gemm_stage<64>(0, d1, 24, nullptr, 1, pwl, DFF, DD, 3, d0, sm);
        gsync(gen);
        xb = (d0 == P[0]) ? 0 : 1;
    }

    // ln_f (blocks 0..3), reducing final partials (XCH chunks)
    if (blk < BB) {
        const float* Px = P[xb];
        float v0 = 0.f, v1 = 0.f;
        #pragma unroll 8
        for (int kc = 0; kc < XCH; kc++)
            v0 += __ldcg(&Px[((size_t)kc * BB + blk) * DD + tid]);
        if (tid < 256) {
            #pragma unroll 8
            for (int kc = 0; kc < XCH; kc++)
                v1 += __ldcg(&Px[((size_t)kc * BB + blk) * DD + tid + 512]);
        }
        sm[tid] = v0 + v1; __syncthreads();
        for (int o = 256; o; o >>= 1) { if (tid < o) sm[tid] += sm[tid + o]; __syncthreads(); }
        float mu = sm[0] * (1.0f / DD); __syncthreads();
        float d0 = v0 - mu, d1 = (tid < 256) ? (v1 - mu) : 0.f;
        sm[tid] = d0 * d0 + ((tid < 256) ? d1 * d1 : 0.f); __syncthreads();
        for (int o = 256; o; o >>= 1) { if (tid < o) sm[tid] += sm[tid + o]; __syncthreads(); }
        float rstd = rsqrtf(sm[0] * (1.0f / DD) + 1e-5f);
        __stcg(&g_xn[blk * DD + tid], d0 * rstd * lnw[tid]);
        if (tid < 256) __stcg(&g_xn[blk * DD + tid + 512], d1 * rstd * lnw[tid + 512]);
    }
    gsync(gen);

    // logits: g_logits[b,v] = xn[b,:].wte[v,:]  (warp per vocab row)
    {
        float4* sxn4 = (float4*)sm;
        for (int i = tid; i < BB * DD / 4; i += NT)
            sxn4[i] = __ldcg(&((const float4*)g_xn)[i]);
        __syncthreads();
        for (int v = gw; v < VV; v += NWARP) {
            const float4* wr = (const float4*)(wte + (size_t)v * DD);
            float a0 = 0.f, a1 = 0.f, a2 = 0.f, a3 = 0.f;
            #pragma unroll
            for (int jj = 0; jj < DD / 128; jj++) {
                int j = lane + jj * 32;
                float4 w = wr[j];
                float4 x0 = sxn4[j];
                float4 x1 = sxn4[192 + j];
                float4 x2 = sxn4[384 + j];
                float4 x3 = sxn4[576 + j];
                a0 += w.x * x0.x + w.y * x0.y + w.z * x0.z + w.w * x0.w;
                a1 += w.x * x1.x + w.y * x1.y + w.z * x1.z + w.w * x1.w;
                a2 += w.x * x2.x + w.y * x2.y + w.z * x2.z + w.w * x2.w;
                a3 += w.x * x3.x + w.y * x3.y + w.z * x3.z + w.w * x3.w;
            }
            a0 = warp_sum(a0); a1 = warp_sum(a1); a2 = warp_sum(a2); a3 = warp_sum(a3);
            if (lane == 0) {
                __stcg(&g_logits[v],               a0);
                __stcg(&g_logits[LSTRIDE + v],     a1);
                __stcg(&g_logits[2 * LSTRIDE + v], a2);
                __stcg(&g_logits[3 * LSTRIDE + v], a3);
            }
        }
    }
}

// =============== broadcast: unchanged (at the 5.44 TB/s write roofline) ======
__global__ __launch_bounds__(256)
void k_bcast(float* __restrict__ out) {
    __shared__ __align__(16) float smf[WIN + 4];
    float4* sm4 = (float4*)smf;
    int tid = threadIdx.x, warp = tid >> 5, lane = tid & 31;

    int blk = blockIdx.x;
    int b   = blk & 3;
    int rest = blk >> 2;
    int win = rest % NWIN;
    int rg  = rest / NWIN;

    int w0 = win * WIN;
    int wlen = VV - w0; if (wlen > WIN) wlen = WIN;

    const float* src = g_logits + (size_t)b * LSTRIDE + w0;
    for (int i = tid; i < wlen; i += 256) smf[i] = __ldcg(&src[i]);
    __syncthreads();

    #pragma unroll
    for (int rr = 0; rr < 4; rr++) {
        int r = rg * 32 + rr * 8 + warp;
        int a = r & 3;
        int head = (4 - a) & 3;
        int nvec = (wlen - head) >> 2;
        int tail = wlen - head - 4 * nvec;

        float* dst = out + (size_t)(b * TT + r) * VV + w0;
        if (lane < head) dst[lane] = smf[lane];
        float4* d4 = (float4*)(dst + head);
        if (a == 0) {
            for (int i = lane; i < nvec; i += 32) __stcs(d4 + i, sm4[i]);
        } else if (a == 3) {
            for (int i = lane; i < nvec; i += 32) {
                float4 x = sm4[i], y = sm4[i + 1];
                __stcs(d4 + i, make_float4(x.y, x.z, x.w, y.x));
            }
        } else if (a == 2) {
            for (int i = lane; i < nvec; i += 32) {
                float4 x = sm4[i], y = sm4[i + 1];
                __stcs(d4 + i, make_float4(x.z, x.w, y.x, y.y));
            }
        } else {
            for (int i = lane; i < nvec; i += 32) {
                float4 x = sm4[i], y = sm4[i + 1];
                __stcs(d4 + i, make_float4(x.w, y.x, y.y, y.z));
            }
        }
        if (lane < tail) dst[head + 4 * nvec + lane] = smf[head + 4 * nvec + lane];
    }
}

// ---------------- launch ------------------------------------------------------
extern "C" void kernel_launch(void* const* d_in, const int* in_sizes, int n_in,
                              void* d_out, int out_size) {
    const int*   idx = (const int*)  d_in[0];
    const float* wte = (const float*)d_in[1];
    const float* wpe = (const float*)d_in[2];
    const float* lnw = (const float*)d_in[3];
    // d_in[4]=qw, d_in[5]=qb : dead (scores independent of Q)
    const float* kw  = (const float*)d_in[6];
    const float* kb  = (const float*)d_in[7];
    const float* vw  = (const float*)d_in[8];
    const float* vb  = (const float*)d_in[9];
    const float* fcw = (const float*)d_in[10];
    const float* pw  = (const float*)d_in[11];
    float* out = (float*)d_out;

    k_main<<<NB, NT>>>(idx, wte, wpe, lnw, kw, kb, vw, vb, fcw, pw);
    k_bcast<<<BB * NWIN * RG, 256>>>(out);
}